// round 15
// baseline (speedup 1.0000x reference)
#include <cuda_runtime.h>
#include <cuda_fp16.h>
#include <cstdint>
#include <cstddef>

#define BSZ 2
#define SEQ 2048
#define DIM 2048
#define NH 32
#define NKV 8
#define HD 64
#define QKV_N ((NH + 2*NKV)*HD)   // 3072

// ---------------- scratch (static device globals; no allocation) -----------
__device__ __half g_x  [(size_t)BSZ*SEQ*DIM];
__device__ __half g_wq [(size_t)QKV_N*DIM];
__device__ __half g_ao [(size_t)BSZ*SEQ*DIM];
__device__ __half g_wo [(size_t)DIM*DIM];

__device__ __half g_q  [(size_t)BSZ*NH *SEQ*HD];   // [b,h,s,d] (pre-scaled 1/8)
__device__ __half g_k  [(size_t)BSZ*NKV*SEQ*HD];   // [b,kv,s,d]
__device__ __half g_v  [(size_t)BSZ*NKV*HD*SEQ];   // [b,kv,d,s] transposed

// ---------------- small PTX helpers (sm_80-baseline ISA only) ---------------
__device__ __forceinline__ uint32_t smem_to_u32(const void* p) {
    uint32_t a;
    asm("{ .reg .u64 t; cvta.to.shared.u64 t, %1; cvt.u32.u64 %0, t; }"
        : "=r"(a) : "l"(p));
    return a;
}
__device__ __forceinline__ void cp_async16(uint32_t dst, const void* src) {
    asm volatile("cp.async.cg.shared.global [%0], [%1], 16;"
                 :: "r"(dst), "l"(src) : "memory");
}
#define CP_COMMIT() asm volatile("cp.async.commit_group;" ::: "memory")
#define CP_WAIT0()  asm volatile("cp.async.wait_group 0;" ::: "memory")

__device__ __forceinline__ void ldsm4(uint32_t* r, uint32_t addr) {
    asm volatile("ldmatrix.sync.aligned.m8n8.x4.shared.b16 {%0,%1,%2,%3}, [%4];"
        : "=r"(r[0]), "=r"(r[1]), "=r"(r[2]), "=r"(r[3]) : "r"(addr));
}

// D += A(16x16 fp16) * B(16x8 fp16), fp32 accum
__device__ __forceinline__ void mma16816(float* d, const uint32_t* a,
                                         const uint32_t* b) {
    asm volatile(
        "mma.sync.aligned.m16n8k16.row.col.f32.f16.f16.f32 "
        "{%0,%1,%2,%3}, {%4,%5,%6,%7}, {%8,%9}, {%0,%1,%2,%3};"
        : "+f"(d[0]), "+f"(d[1]), "+f"(d[2]), "+f"(d[3])
        : "r"(a[0]), "r"(a[1]), "r"(a[2]), "r"(a[3]), "r"(b[0]), "r"(b[1]));
}

// D += A * B, fp16 accum (2 packed regs: {c0,c1}=row g, {c2,c3}=row g+8)
__device__ __forceinline__ void mma16816h(uint32_t* d, const uint32_t* a,
                                          const uint32_t* b) {
    asm volatile(
        "mma.sync.aligned.m16n8k16.row.col.f16.f16.f16.f16 "
        "{%0,%1}, {%2,%3,%4,%5}, {%6,%7}, {%0,%1};"
        : "+r"(d[0]), "+r"(d[1])
        : "r"(a[0]), "r"(a[1]), "r"(a[2]), "r"(a[3]), "r"(b[0]), "r"(b[1]));
}

// ---------------- fused conversion kernel (x, wqkv, wo in one launch) --------
#define CN1 (BSZ*SEQ*DIM/4)        // 2097152
#define CN2 (QKV_N*DIM/4)          // 1572864
#define CN3 (DIM*DIM/4)            // 1048576

__global__ void conv_all_kernel(const float* __restrict__ x,
                                const float* __restrict__ wq,
                                const float* __restrict__ wo)
{
    int i = blockIdx.x * 256 + threadIdx.x;
    const float* src;
    __half* dst;
    int j;
    if (i < CN1)              { src = x;  dst = g_x;  j = i; }
    else if (i < CN1 + CN2)   { src = wq; dst = g_wq; j = i - CN1; }
    else                      { src = wo; dst = g_wo; j = i - CN1 - CN2; }
    float4 v = ((const float4*)src)[j];
    ((__half2*)dst)[2*j]   = __floats2half2_rn(v.x, v.y);
    ((__half2*)dst)[2*j+1] = __floats2half2_rn(v.z, v.w);
}

// ---------------- GEMM core (shared mainloop) --------------------------------
// K-chunk 64, 2-stage cp.async pipeline, 128x128 tiles, 8 warps.
#define GSTR 72
#define TILE_BYTES (128 * GSTR * 2)             // 18432
#define GT_SMEM_BYTES (2 * 2 * TILE_BYTES)      // 73728

struct GemmCtx {
    int wm, wn, lr, lc;
    float acc[4][4][4];
};

__device__ __forceinline__ void gemm_mainloop(
    GemmCtx& cx, const __half* A, const __half* B,
    uint32_t sbase, int bm, int bn, int K)
{
    const int t    = threadIdx.x;
    const int wid  = t >> 5, lane = t & 31;
    cx.wm = (wid & 1) * 64;
    cx.wn = (wid >> 1) * 32;
    cx.lr = lane >> 2;
    cx.lc = lane & 3;

    const int arow = (lane & 7) + ((lane >> 3) & 1) * 8;
    const int acol = (lane >> 4) * 8;
    const uint32_t aoff = (uint32_t)(arow * GSTR + acol) * 2;
    const int brow = (lane & 7) + ((lane >> 4) & 1) * 8;
    const int bcol = ((lane >> 3) & 1) * 8;
    const uint32_t boff = (uint32_t)(brow * GSTR + bcol) * 2;

#pragma unroll
    for (int mi = 0; mi < 4; ++mi)
#pragma unroll
        for (int ni = 0; ni < 4; ++ni)
#pragma unroll
            for (int q = 0; q < 4; ++q) cx.acc[mi][ni][q] = 0.f;

    const int nch = K / 64;

    auto load_chunk = [&](int buf, int kc) {
        const __half* gA = A + (size_t)bm * K + kc * 64;
        const __half* gB = B + (size_t)bn * K + kc * 64;
        const uint32_t sdA = sbase + buf * 2 * TILE_BYTES;
        const uint32_t sdB = sdA + TILE_BYTES;
#pragma unroll
        for (int i = 0; i < 4; ++i) {
            int c   = t + i * 256;
            int row = c >> 3, cc = c & 7;
            cp_async16(sdA + (uint32_t)(row * GSTR * 2) + cc * 16,
                       gA + (size_t)row * K + cc * 8);
            cp_async16(sdB + (uint32_t)(row * GSTR * 2) + cc * 16,
                       gB + (size_t)row * K + cc * 8);
        }
    };

    load_chunk(0, 0); CP_COMMIT();

    for (int c = 0; c < nch; ++c) {
        CP_WAIT0();
        __syncthreads();
        if (c + 1 < nch) { load_chunk((c + 1) & 1, c + 1); CP_COMMIT(); }

        const int buf = c & 1;
        const uint32_t uA = sbase + buf * 2 * TILE_BYTES;
        const uint32_t uB = uA + TILE_BYTES;

#pragma unroll
        for (int ks = 0; ks < 4; ++ks) {
            uint32_t a4[4][4], b4[2][4];
#pragma unroll
            for (int mi = 0; mi < 4; ++mi) {
                const uint32_t ra = (uint32_t)((cx.wm + mi * 16) * GSTR) * 2 + ks * 32;
                ldsm4(a4[mi], uA + ra + aoff);
            }
#pragma unroll
            for (int p = 0; p < 2; ++p) {
                const uint32_t rb = (uint32_t)((cx.wn + p * 16) * GSTR) * 2 + ks * 32;
                ldsm4(b4[p], uB + rb + boff);
            }
#pragma unroll
            for (int mi = 0; mi < 4; ++mi)
#pragma unroll
                for (int ni = 0; ni < 4; ++ni)
                    mma16816(cx.acc[mi][ni], a4[mi], &b4[ni >> 1][(ni & 1) * 2]);
        }
    }
}

// QKV GEMM with fused RoPE + Q/K/V scatter.
__global__ __launch_bounds__(256, 2)
void gemm_qkv_kernel(const __half* __restrict__ A,
                     const __half* __restrict__ B,
                     const float* __restrict__ fc, int K)
{
    extern __shared__ __half sm[];
    const uint32_t sbase = smem_to_u32(sm);
    const int bm = blockIdx.y * 128, bn = blockIdx.x * 128;
    const int t  = threadIdx.x;

    GemmCtx cx;
    gemm_mainloop(cx, A, B, sbase, bm, bn, K);

    if (bn >= DIM + NKV * HD) {
        // ---- V: stage acc into smem as [d][s], then coalesced store ----
        __syncthreads();
#pragma unroll
        for (int mi = 0; mi < 4; ++mi) {
#pragma unroll
            for (int ni = 0; ni < 4; ++ni) {
                const int d = cx.wn + ni * 8 + cx.lc * 2;
                const float* a = cx.acc[mi][ni];
#pragma unroll
                for (int rh = 0; rh < 2; ++rh) {
                    const int s = cx.wm + mi * 16 + cx.lr + rh * 8;
                    sm[(d    ) * 136 + s] = __float2half_rn(a[rh*2+0]);
                    sm[(d + 1) * 136 + s] = __float2half_rn(a[rh*2+1]);
                }
            }
        }
        __syncthreads();
        const int c2b = bn - DIM - NKV * HD;
        const int b = bm >> 11;
        const int s0 = bm & (SEQ - 1);
#pragma unroll
        for (int it = 0; it < 8; ++it) {
            int idx = t + it * 256;
            int d  = idx >> 4, sc = (idx & 15) * 8;
            int kv = (c2b + d) >> 6, dd = (c2b + d) & 63;
            uint4 val = *(const uint4*)&sm[d * 136 + sc];
            *(uint4*)&g_v[(((size_t)(b * NKV + kv)) * HD + dd) * SEQ + s0 + sc] = val;
        }
        return;
    }

#pragma unroll
    for (int mi = 0; mi < 4; ++mi) {
        const int row = bm + cx.wm + mi * 16 + cx.lr;
#pragma unroll
        for (int ni = 0; ni < 4; ++ni) {
            const int col = bn + cx.wn + ni * 8 + cx.lc * 2;
            const float* a = cx.acc[mi][ni];
            if (bn < DIM) {
                const int h = col >> 6, d = col & 63;
#pragma unroll
                for (int rh = 0; rh < 2; ++rh) {
                    const int r = row + rh * 8;
                    const int s = r & (SEQ - 1), b = r >> 11;
                    float2 cs = *(const float2*)&fc[s * HD + d];
                    float v0 = (a[rh*2+0] * cs.x - a[rh*2+1] * cs.y) * 0.125f;
                    float v1 = (a[rh*2+1] * cs.x + a[rh*2+0] * cs.y) * 0.125f;
                    *(__half2*)&g_q[(((size_t)(b*NH+h))*SEQ + s)*HD + d] =
                        __floats2half2_rn(v0, v1);
                }
            } else {
                const int c2 = col - DIM;
                const int kv = c2 >> 6, d = c2 & 63;
#pragma unroll
                for (int rh = 0; rh < 2; ++rh) {
                    const int r = row + rh * 8;
                    const int s = r & (SEQ - 1), b = r >> 11;
                    float2 cs = *(const float2*)&fc[s * HD + d];
                    float v0 = a[rh*2+0] * cs.x - a[rh*2+1] * cs.y;
                    float v1 = a[rh*2+1] * cs.x + a[rh*2+0] * cs.y;
                    *(__half2*)&g_k[(((size_t)(b*NKV+kv))*SEQ + s)*HD + d] =
                        __floats2half2_rn(v0, v1);
                }
            }
        }
    }
}

// Generic GEMM: C fp32 = A[M,K] * B[N,K]^T (out-projection)
__global__ __launch_bounds__(256, 2)
void gemm_hmma_kernel(const __half* __restrict__ A,
                      const __half* __restrict__ B,
                      float* __restrict__ C, int M, int N, int K)
{
    extern __shared__ __half sm[];
    const uint32_t sbase = smem_to_u32(sm);
    const int bm = blockIdx.y * 128, bn = blockIdx.x * 128;

    GemmCtx cx;
    gemm_mainloop(cx, A, B, sbase, bm, bn, K);

#pragma unroll
    for (int mi = 0; mi < 4; ++mi) {
        const int row = bm + cx.wm + mi * 16 + cx.lr;
#pragma unroll
        for (int ni = 0; ni < 4; ++ni) {
            const int col = bn + cx.wn + ni * 8 + cx.lc * 2;
            *(float2*)&C[(size_t)row * N + col] =
                make_float2(cx.acc[mi][ni][0], cx.acc[mi][ni][1]);
            *(float2*)&C[(size_t)(row + 8) * N + col] =
                make_float2(cx.acc[mi][ni][2], cx.acc[mi][ni][3]);
        }
    }
}

// ---------------- flash attention on HMMA ------------------------------------
// Paired Q-tiles (uniform 34 KV-tiles/CTA). S: fp32-acc MMA. PV: fp16-acc MMA
// per KV tile, promoted to fp32 with the alpha rescale.
#define FSTR 72
#define FTILE_BYTES (64 * FSTR * 2)   // 9216

__global__ __launch_bounds__(256, 2)
void flash_hmma_kernel()
{
    __shared__ __half sK[2][64 * FSTR];
    __shared__ __half sV[2][64 * FSTR];   // [d][key]

    const int t = threadIdx.x;
    const int w = t >> 5, lane = t & 31;
    const int g = lane >> 2, tg = lane & 3;
    const int bx = blockIdx.x, h = blockIdx.y, b = blockIdx.z;
    const int kvh = h >> 2;

    const uint32_t uK0 = smem_to_u32(sK);
    const uint32_t uV0 = smem_to_u32(sV);

    const int brow = (lane & 7) + ((lane >> 4) & 1) * 8;
    const int bcol = ((lane >> 3) & 1) * 8;
    const uint32_t boff = (uint32_t)(brow * FSTR + bcol) * 2;

    const __half* gk = g_k + ((size_t)(b * NKV + kvh)) * SEQ * HD;
    const __half* gv = g_v + ((size_t)(b * NKV + kvh)) * HD * SEQ;

    auto load_tile = [&](int buf, int jb) {
#pragma unroll
        for (int cc = 0; cc < 2; ++cc) {
            int c   = t + cc * 256;
            int row = c >> 3, col = (c & 7) * 8;
            uint32_t so = (uint32_t)buf * FTILE_BYTES + (uint32_t)(row * FSTR + col) * 2;
            cp_async16(uK0 + so, &gk[(size_t)(jb * 64 + row) * HD + col]);
            cp_async16(uV0 + so, &gv[(size_t)row * SEQ + jb * 64 + col]);
        }
    };

    const float L2E = 1.4426950408889634f;

#pragma unroll 1
    for (int pass = 0; pass < 2; ++pass) {
        const int qb = pass ? (15 - bx) : bx;
        const int qrow0 = qb * 128 + w * 16;

        uint32_t qf[4][4];
        {
            const __half* gq = g_q + (((size_t)(b*NH+h))*SEQ + qrow0)*HD;
#pragma unroll
            for (int kk = 0; kk < 4; ++kk) {
                int d0 = kk * 16 + tg * 2;
                qf[kk][0] = *(const uint32_t*)&gq[(size_t)(g    ) * HD + d0];
                qf[kk][1] = *(const uint32_t*)&gq[(size_t)(g + 8) * HD + d0];
                qf[kk][2] = *(const uint32_t*)&gq[(size_t)(g    ) * HD + d0 + 8];
                qf[kk][3] = *(const uint32_t*)&gq[(size_t)(g + 8) * HD + d0 + 8];
            }
        }

        float m0 = -1e30f, m1 = -1e30f, l0 = 0.f, l1 = 0.f;
        float o[8][4];
#pragma unroll
        for (int ni = 0; ni < 8; ++ni)
#pragma unroll
            for (int q = 0; q < 4; ++q) o[ni][q] = 0.f;

        const int ntile = 2 * qb + 2;
        load_tile(0, 0); CP_COMMIT();

        for (int jb = 0; jb < ntile; ++jb) {
            const int buf = jb & 1;
            CP_WAIT0();
            __syncthreads();
            if (jb + 1 < ntile) { load_tile(buf ^ 1, jb + 1); CP_COMMIT(); }

            if (jb * 64 <= qrow0 + 15) {
                const uint32_t uK = uK0 + buf * FTILE_BYTES;
                const uint32_t uV = uV0 + buf * FTILE_BYTES;

                // S = Q K^T (fp32 accum)
                float s[8][4];
#pragma unroll
                for (int ni = 0; ni < 8; ++ni)
                    s[ni][0] = s[ni][1] = s[ni][2] = s[ni][3] = 0.f;

#pragma unroll
                for (int kk = 0; kk < 4; ++kk)
#pragma unroll
                    for (int p = 0; p < 4; ++p) {
                        const uint32_t rb = (uint32_t)(p * 16 * FSTR) * 2 + kk * 32;
                        uint32_t k4[4];
                        ldsm4(k4, uK + rb + boff);
                        mma16816(s[2*p],   qf[kk], k4 + 0);
                        mma16816(s[2*p+1], qf[kk], k4 + 2);
                    }

                // causal mask (diagonal tiles only)
                if (jb * 64 + 63 > qrow0) {
                    const int cb = jb * 64 + tg * 2;
                    const int r0 = qrow0 + g, r1 = r0 + 8;
#pragma unroll
                    for (int ni = 0; ni < 8; ++ni) {
                        int c0 = cb + ni * 8, c1 = c0 + 1;
                        if (c0 > r0) s[ni][0] = -1e30f;
                        if (c1 > r0) s[ni][1] = -1e30f;
                        if (c0 > r1) s[ni][2] = -1e30f;
                        if (c1 > r1) s[ni][3] = -1e30f;
                    }
                }

                // online softmax: max in fp32, exp via ex2.approx.f16x2
                float mt0 = -1e30f, mt1 = -1e30f;
#pragma unroll
                for (int ni = 0; ni < 8; ++ni) {
                    mt0 = fmaxf(mt0, fmaxf(s[ni][0], s[ni][1]));
                    mt1 = fmaxf(mt1, fmaxf(s[ni][2], s[ni][3]));
                }
                mt0 = fmaxf(mt0, __shfl_xor_sync(0xffffffffu, mt0, 1));
                mt0 = fmaxf(mt0, __shfl_xor_sync(0xffffffffu, mt0, 2));
                mt1 = fmaxf(mt1, __shfl_xor_sync(0xffffffffu, mt1, 1));
                mt1 = fmaxf(mt1, __shfl_xor_sync(0xffffffffu, mt1, 2));
                float mn0 = fmaxf(m0, mt0), mn1 = fmaxf(m1, mt1);
                float a0 = __expf(m0 - mn0), a1 = __expf(m1 - mn1);
                m0 = mn0; m1 = mn1;
                const float b0 = mn0 * L2E, b1 = mn1 * L2E;

                uint32_t pe0[8], pe1[8];
                float rs0 = 0.f, rs1 = 0.f;
#pragma unroll
                for (int ni = 0; ni < 8; ++ni) {
                    __half2 e01 = h2exp2(__floats2half2_rn(
                        fmaf(s[ni][0], L2E, -b0), fmaf(s[ni][1], L2E, -b0)));
                    __half2 e23 = h2exp2(__floats2half2_rn(
                        fmaf(s[ni][2], L2E, -b1), fmaf(s[ni][3], L2E, -b1)));
                    pe0[ni] = *(uint32_t*)&e01;
                    pe1[ni] = *(uint32_t*)&e23;
                    float2 f01 = __half22float2(e01);
                    float2 f23 = __half22float2(e23);
                    rs0 += f01.x + f01.y;
                    rs1 += f23.x + f23.y;
                }
                l0 = l0 * a0 + rs0;
                l1 = l1 * a1 + rs1;
#pragma unroll
                for (int ni = 0; ni < 8; ++ni) {
                    o[ni][0] *= a0; o[ni][1] *= a0;
                    o[ni][2] *= a1; o[ni][3] *= a1;
                }

                // O_tile = P V in fp16 accumulators (zeroed per tile)
                uint32_t pacc[8][2];
#pragma unroll
                for (int ni = 0; ni < 8; ++ni) { pacc[ni][0] = 0u; pacc[ni][1] = 0u; }

#pragma unroll
                for (int kk = 0; kk < 4; ++kk) {
                    uint32_t ph[4];
                    ph[0] = pe0[2*kk];     ph[1] = pe1[2*kk];
                    ph[2] = pe0[2*kk + 1]; ph[3] = pe1[2*kk + 1];
#pragma unroll
                    for (int p = 0; p < 4; ++p) {
                        const uint32_t rb = (uint32_t)(p * 16 * FSTR) * 2 + kk * 32;
                        uint32_t v4[4];
                        ldsm4(v4, uV + rb + boff);
                        mma16816h(pacc[2*p],   ph, v4 + 0);
                        mma16816h(pacc[2*p+1], ph, v4 + 2);
                    }
                }
                // promote tile partial into fp32 o
#pragma unroll
                for (int ni = 0; ni < 8; ++ni) {
                    float2 f01 = __half22float2(*(__half2*)&pacc[ni][0]);
                    float2 f23 = __half22float2(*(__half2*)&pacc[ni][1]);
                    o[ni][0] += f01.x; o[ni][1] += f01.y;
                    o[ni][2] += f23.x; o[ni][3] += f23.y;
                }
            }
        }

        // finalize this pass
        l0 += __shfl_xor_sync(0xffffffffu, l0, 1);
        l0 += __shfl_xor_sync(0xffffffffu, l0, 2);
        l1 += __shfl_xor_sync(0xffffffffu, l1, 1);
        l1 += __shfl_xor_sync(0xffffffffu, l1, 2);
        const float inv0 = 1.f / l0, inv1 = 1.f / l1;

        const int r0 = qrow0 + g, r1 = r0 + 8;
#pragma unroll
        for (int ni = 0; ni < 8; ++ni) {
            const int col = h * HD + ni * 8 + tg * 2;
            *(__half2*)&g_ao[(size_t)(b * SEQ + r0) * DIM + col] =
                __floats2half2_rn(o[ni][0] * inv0, o[ni][1] * inv0);
            *(__half2*)&g_ao[(size_t)(b * SEQ + r1) * DIM + col] =
                __floats2half2_rn(o[ni][2] * inv1, o[ni][3] * inv1);
        }
        __syncthreads();   // pass state / smem reuse boundary
    }
}

// ---------------- launcher ---------------------------------------------------
extern "C" void kernel_launch(void* const* d_in, const int* in_sizes, int n_in,
                              void* d_out, int out_size)
{
    const float* x     = (const float*)d_in[0];   // [2,2048,2048]
    const float* fc    = (const float*)d_in[1];   // [2048,32,2]
    // d_in[2] = mask (causal, hardcoded)
    const float* wqkv  = (const float*)d_in[3];   // [3072,2048]
    const float* wo    = (const float*)d_in[4];   // [2048,2048]
    float* out = (float*)d_out;                   // [2,2048,2048]

    void *p_x, *p_wq, *p_ao, *p_wo;
    cudaGetSymbolAddress(&p_x,  g_x);
    cudaGetSymbolAddress(&p_wq, g_wq);
    cudaGetSymbolAddress(&p_ao, g_ao);
    cudaGetSymbolAddress(&p_wo, g_wo);

    cudaFuncSetAttribute(gemm_qkv_kernel,
                         cudaFuncAttributeMaxDynamicSharedMemorySize, GT_SMEM_BYTES);
    cudaFuncSetAttribute(gemm_hmma_kernel,
                         cudaFuncAttributeMaxDynamicSharedMemorySize, GT_SMEM_BYTES);

    const int M = BSZ * SEQ;                      // 4096

    // 0) all fp32 -> fp16 conversions in one launch
    conv_all_kernel<<<(CN1 + CN2 + CN3) / 256, 256>>>(x, wqkv, wo);

    // 1) QKV projection with fused RoPE + scatter -> g_q / g_k / g_v
    gemm_qkv_kernel<<<dim3(QKV_N / 128, M / 128), 256, GT_SMEM_BYTES>>>(
        (const __half*)p_x, (const __half*)p_wq, fc, DIM);

    // 2) causal flash attention (paired Q-tiles) -> g_ao [b,s,h*d] (fp16)
    flash_hmma_kernel<<<dim3(SEQ / 256, NH, BSZ), 256>>>();

    // 3) output projection -> fp32
    gemm_hmma_kernel<<<dim3(DIM / 128, M / 128), 256, GT_SMEM_BYTES>>>(
        (const __half*)p_ao, (const __half*)p_wo,
        out, M, DIM, DIM);
}

// round 16
// speedup vs baseline: 1.0202x; 1.0202x over previous
#include <cuda_runtime.h>
#include <cuda_fp16.h>
#include <cstdint>
#include <cstddef>

#define BSZ 2
#define SEQ 2048
#define DIM 2048
#define NH 32
#define NKV 8
#define HD 64
#define QKV_N ((NH + 2*NKV)*HD)   // 3072

// ---------------- scratch (static device globals; no allocation) -----------
__device__ __half g_x  [(size_t)BSZ*SEQ*DIM];
__device__ __half g_wq [(size_t)QKV_N*DIM];
__device__ __half g_ao [(size_t)BSZ*SEQ*DIM];
__device__ __half g_wo [(size_t)DIM*DIM];

__device__ __half g_q  [(size_t)BSZ*NH *SEQ*HD];   // [b,h,s,d] (pre-scaled 1/8)
__device__ __half g_k  [(size_t)BSZ*NKV*SEQ*HD];   // [b,kv,s,d]
__device__ __half g_v  [(size_t)BSZ*NKV*HD*SEQ];   // [b,kv,d,s] transposed

// ---------------- small PTX helpers (sm_80-baseline ISA only) ---------------
__device__ __forceinline__ uint32_t smem_to_u32(const void* p) {
    uint32_t a;
    asm("{ .reg .u64 t; cvta.to.shared.u64 t, %1; cvt.u32.u64 %0, t; }"
        : "=r"(a) : "l"(p));
    return a;
}
__device__ __forceinline__ void cp_async16(uint32_t dst, const void* src) {
    asm volatile("cp.async.cg.shared.global [%0], [%1], 16;"
                 :: "r"(dst), "l"(src) : "memory");
}
#define CP_COMMIT() asm volatile("cp.async.commit_group;" ::: "memory")
#define CP_WAIT0()  asm volatile("cp.async.wait_group 0;" ::: "memory")

__device__ __forceinline__ void ldsm4(uint32_t* r, uint32_t addr) {
    asm volatile("ldmatrix.sync.aligned.m8n8.x4.shared.b16 {%0,%1,%2,%3}, [%4];"
        : "=r"(r[0]), "=r"(r[1]), "=r"(r[2]), "=r"(r[3]) : "r"(addr));
}

// D += A(16x16 fp16) * B(16x8 fp16), fp32 accum
__device__ __forceinline__ void mma16816(float* d, const uint32_t* a,
                                         const uint32_t* b) {
    asm volatile(
        "mma.sync.aligned.m16n8k16.row.col.f32.f16.f16.f32 "
        "{%0,%1,%2,%3}, {%4,%5,%6,%7}, {%8,%9}, {%0,%1,%2,%3};"
        : "+f"(d[0]), "+f"(d[1]), "+f"(d[2]), "+f"(d[3])
        : "r"(a[0]), "r"(a[1]), "r"(a[2]), "r"(a[3]), "r"(b[0]), "r"(b[1]));
}

// ---------------- conversion kernel (x + wqkv only) --------------------------
#define CN1 (BSZ*SEQ*DIM/4)        // 2097152
#define CN2 (QKV_N*DIM/4)          // 1572864

__global__ void conv_xw_kernel(const float* __restrict__ x,
                               const float* __restrict__ wq)
{
    int i = blockIdx.x * 256 + threadIdx.x;
    const float* src;
    __half* dst;
    int j;
    if (i < CN1) { src = x;  dst = g_x;  j = i; }
    else         { src = wq; dst = g_wq; j = i - CN1; }
    float4 v = ((const float4*)src)[j];
    ((__half2*)dst)[2*j]   = __floats2half2_rn(v.x, v.y);
    ((__half2*)dst)[2*j+1] = __floats2half2_rn(v.z, v.w);
}

// ---------------- GEMM core (shared mainloop) --------------------------------
// K-chunk 64, 2-stage cp.async pipeline, 128x128 tiles, 8 warps.
#define GSTR 72
#define TILE_BYTES (128 * GSTR * 2)             // 18432
#define GT_SMEM_BYTES (2 * 2 * TILE_BYTES)      // 73728

struct GemmCtx {
    int wm, wn, lr, lc;
    float acc[4][4][4];
};

__device__ __forceinline__ void gemm_mainloop(
    GemmCtx& cx, const __half* A, const __half* B,
    uint32_t sbase, int bm, int bn, int K)
{
    const int t    = threadIdx.x;
    const int wid  = t >> 5, lane = t & 31;
    cx.wm = (wid & 1) * 64;
    cx.wn = (wid >> 1) * 32;
    cx.lr = lane >> 2;
    cx.lc = lane & 3;

    const int arow = (lane & 7) + ((lane >> 3) & 1) * 8;
    const int acol = (lane >> 4) * 8;
    const uint32_t aoff = (uint32_t)(arow * GSTR + acol) * 2;
    const int brow = (lane & 7) + ((lane >> 4) & 1) * 8;
    const int bcol = ((lane >> 3) & 1) * 8;
    const uint32_t boff = (uint32_t)(brow * GSTR + bcol) * 2;

#pragma unroll
    for (int mi = 0; mi < 4; ++mi)
#pragma unroll
        for (int ni = 0; ni < 4; ++ni)
#pragma unroll
            for (int q = 0; q < 4; ++q) cx.acc[mi][ni][q] = 0.f;

    const int nch = K / 64;

    auto load_chunk = [&](int buf, int kc) {
        const __half* gA = A + (size_t)bm * K + kc * 64;
        const __half* gB = B + (size_t)bn * K + kc * 64;
        const uint32_t sdA = sbase + buf * 2 * TILE_BYTES;
        const uint32_t sdB = sdA + TILE_BYTES;
#pragma unroll
        for (int i = 0; i < 4; ++i) {
            int c   = t + i * 256;
            int row = c >> 3, cc = c & 7;
            cp_async16(sdA + (uint32_t)(row * GSTR * 2) + cc * 16,
                       gA + (size_t)row * K + cc * 8);
            cp_async16(sdB + (uint32_t)(row * GSTR * 2) + cc * 16,
                       gB + (size_t)row * K + cc * 8);
        }
    };

    load_chunk(0, 0); CP_COMMIT();

    for (int c = 0; c < nch; ++c) {
        CP_WAIT0();
        __syncthreads();
        if (c + 1 < nch) { load_chunk((c + 1) & 1, c + 1); CP_COMMIT(); }

        const int buf = c & 1;
        const uint32_t uA = sbase + buf * 2 * TILE_BYTES;
        const uint32_t uB = uA + TILE_BYTES;

#pragma unroll
        for (int ks = 0; ks < 4; ++ks) {
            uint32_t a4[4][4], b4[2][4];
#pragma unroll
            for (int mi = 0; mi < 4; ++mi) {
                const uint32_t ra = (uint32_t)((cx.wm + mi * 16) * GSTR) * 2 + ks * 32;
                ldsm4(a4[mi], uA + ra + aoff);
            }
#pragma unroll
            for (int p = 0; p < 2; ++p) {
                const uint32_t rb = (uint32_t)((cx.wn + p * 16) * GSTR) * 2 + ks * 32;
                ldsm4(b4[p], uB + rb + boff);
            }
#pragma unroll
            for (int mi = 0; mi < 4; ++mi)
#pragma unroll
                for (int ni = 0; ni < 4; ++ni)
                    mma16816(cx.acc[mi][ni], a4[mi], &b4[ni >> 1][(ni & 1) * 2]);
        }
    }
}

// QKV GEMM with fused RoPE + Q/K/V scatter.
__global__ __launch_bounds__(256, 2)
void gemm_qkv_kernel(const __half* __restrict__ A,
                     const __half* __restrict__ B,
                     const float* __restrict__ fc, int K)
{
    extern __shared__ __half sm[];
    const uint32_t sbase = smem_to_u32(sm);
    const int bm = blockIdx.y * 128, bn = blockIdx.x * 128;
    const int t  = threadIdx.x;

    GemmCtx cx;
    gemm_mainloop(cx, A, B, sbase, bm, bn, K);

    if (bn >= DIM + NKV * HD) {
        // ---- V: stage acc into smem as [d][s], then coalesced store ----
        __syncthreads();
#pragma unroll
        for (int mi = 0; mi < 4; ++mi) {
#pragma unroll
            for (int ni = 0; ni < 4; ++ni) {
                const int d = cx.wn + ni * 8 + cx.lc * 2;
                const float* a = cx.acc[mi][ni];
#pragma unroll
                for (int rh = 0; rh < 2; ++rh) {
                    const int s = cx.wm + mi * 16 + cx.lr + rh * 8;
                    sm[(d    ) * 136 + s] = __float2half_rn(a[rh*2+0]);
                    sm[(d + 1) * 136 + s] = __float2half_rn(a[rh*2+1]);
                }
            }
        }
        __syncthreads();
        const int c2b = bn - DIM - NKV * HD;
        const int b = bm >> 11;
        const int s0 = bm & (SEQ - 1);
#pragma unroll
        for (int it = 0; it < 8; ++it) {
            int idx = t + it * 256;
            int d  = idx >> 4, sc = (idx & 15) * 8;
            int kv = (c2b + d) >> 6, dd = (c2b + d) & 63;
            uint4 val = *(const uint4*)&sm[d * 136 + sc];
            *(uint4*)&g_v[(((size_t)(b * NKV + kv)) * HD + dd) * SEQ + s0 + sc] = val;
        }
        return;
    }

#pragma unroll
    for (int mi = 0; mi < 4; ++mi) {
        const int row = bm + cx.wm + mi * 16 + cx.lr;
#pragma unroll
        for (int ni = 0; ni < 4; ++ni) {
            const int col = bn + cx.wn + ni * 8 + cx.lc * 2;
            const float* a = cx.acc[mi][ni];
            if (bn < DIM) {
                const int h = col >> 6, d = col & 63;
#pragma unroll
                for (int rh = 0; rh < 2; ++rh) {
                    const int r = row + rh * 8;
                    const int s = r & (SEQ - 1), b = r >> 11;
                    float2 cs = *(const float2*)&fc[s * HD + d];
                    float v0 = (a[rh*2+0] * cs.x - a[rh*2+1] * cs.y) * 0.125f;
                    float v1 = (a[rh*2+1] * cs.x + a[rh*2+0] * cs.y) * 0.125f;
                    *(__half2*)&g_q[(((size_t)(b*NH+h))*SEQ + s)*HD + d] =
                        __floats2half2_rn(v0, v1);
                }
            } else {
                const int c2 = col - DIM;
                const int kv = c2 >> 6, d = c2 & 63;
#pragma unroll
                for (int rh = 0; rh < 2; ++rh) {
                    const int r = row + rh * 8;
                    const int s = r & (SEQ - 1), b = r >> 11;
                    float2 cs = *(const float2*)&fc[s * HD + d];
                    float v0 = a[rh*2+0] * cs.x - a[rh*2+1] * cs.y;
                    float v1 = a[rh*2+1] * cs.x + a[rh*2+0] * cs.y;
                    *(__half2*)&g_k[(((size_t)(b*NKV+kv))*SEQ + s)*HD + d] =
                        __floats2half2_rn(v0, v1);
                }
            }
        }
    }
}

// Generic GEMM: C fp32 = A[M,K] * B[N,K]^T (out-projection)
__global__ __launch_bounds__(256, 2)
void gemm_hmma_kernel(const __half* __restrict__ A,
                      const __half* __restrict__ B,
                      float* __restrict__ C, int M, int N, int K)
{
    extern __shared__ __half sm[];
    const uint32_t sbase = smem_to_u32(sm);
    const int bm = blockIdx.y * 128, bn = blockIdx.x * 128;

    GemmCtx cx;
    gemm_mainloop(cx, A, B, sbase, bm, bn, K);

#pragma unroll
    for (int mi = 0; mi < 4; ++mi) {
        const int row = bm + cx.wm + mi * 16 + cx.lr;
#pragma unroll
        for (int ni = 0; ni < 4; ++ni) {
            const int col = bn + cx.wn + ni * 8 + cx.lc * 2;
            *(float2*)&C[(size_t)row * N + col] =
                make_float2(cx.acc[mi][ni][0], cx.acc[mi][ni][1]);
            *(float2*)&C[(size_t)(row + 8) * N + col] =
                make_float2(cx.acc[mi][ni][2], cx.acc[mi][ni][3]);
        }
    }
}

// ---------------- flash attention on HMMA ------------------------------------
// Paired Q-tiles (uniform 34 KV-tiles/CTA), fp32-acc PV (round-14 math).
// Prologue: each CTA converts its slice of wo fp32->fp16 (hides under MMA).
#define FSTR 72
#define FTILE_BYTES (64 * FSTR * 2)   // 9216

__global__ __launch_bounds__(256, 2)
void flash_hmma_kernel(const float* __restrict__ wo)
{
    __shared__ __half sK[2][64 * FSTR];
    __shared__ __half sV[2][64 * FSTR];   // [d][key]

    const int t = threadIdx.x;
    const int w = t >> 5, lane = t & 31;
    const int g = lane >> 2, tg = lane & 3;
    const int bx = blockIdx.x, h = blockIdx.y, b = blockIdx.z;
    const int kvh = h >> 2;

    const uint32_t uK0 = smem_to_u32(sK);
    const uint32_t uV0 = smem_to_u32(sV);

    const int brow = (lane & 7) + ((lane >> 4) & 1) * 8;
    const int bcol = ((lane >> 3) & 1) * 8;
    const uint32_t boff = (uint32_t)(brow * FSTR + bcol) * 2;

    const __half* gk = g_k + ((size_t)(b * NKV + kvh)) * SEQ * HD;
    const __half* gv = g_v + ((size_t)(b * NKV + kvh)) * HD * SEQ;

    auto load_tile = [&](int buf, int jb) {
#pragma unroll
        for (int cc = 0; cc < 2; ++cc) {
            int c   = t + cc * 256;
            int row = c >> 3, col = (c & 7) * 8;
            uint32_t so = (uint32_t)buf * FTILE_BYTES + (uint32_t)(row * FSTR + col) * 2;
            cp_async16(uK0 + so, &gk[(size_t)(jb * 64 + row) * HD + col]);
            cp_async16(uV0 + so, &gv[(size_t)row * SEQ + jb * 64 + col]);
        }
    };

    // ---- fused wo conversion (consumed only by the out-projection kernel;
    //      streaming traffic hidden under this compute-bound kernel) ----
    {
        const int bid = bx + 8 * (h + 32 * b);        // 0..511
#pragma unroll
        for (int i = 0; i < 8; ++i) {
            int j = bid * 2048 + i * 256 + t;         // 512*2048 = DIM*DIM/4
            float4 v = ((const float4*)wo)[j];
            ((__half2*)g_wo)[2*j]   = __floats2half2_rn(v.x, v.y);
            ((__half2*)g_wo)[2*j+1] = __floats2half2_rn(v.z, v.w);
        }
    }

    const float L2E = 1.4426950408889634f;

#pragma unroll 1
    for (int pass = 0; pass < 2; ++pass) {
        const int qb = pass ? (15 - bx) : bx;
        const int qrow0 = qb * 128 + w * 16;

        uint32_t qf[4][4];
        {
            const __half* gq = g_q + (((size_t)(b*NH+h))*SEQ + qrow0)*HD;
#pragma unroll
            for (int kk = 0; kk < 4; ++kk) {
                int d0 = kk * 16 + tg * 2;
                qf[kk][0] = *(const uint32_t*)&gq[(size_t)(g    ) * HD + d0];
                qf[kk][1] = *(const uint32_t*)&gq[(size_t)(g + 8) * HD + d0];
                qf[kk][2] = *(const uint32_t*)&gq[(size_t)(g    ) * HD + d0 + 8];
                qf[kk][3] = *(const uint32_t*)&gq[(size_t)(g + 8) * HD + d0 + 8];
            }
        }

        float m0 = -1e30f, m1 = -1e30f, l0 = 0.f, l1 = 0.f;
        float o[8][4];
#pragma unroll
        for (int ni = 0; ni < 8; ++ni)
#pragma unroll
            for (int q = 0; q < 4; ++q) o[ni][q] = 0.f;

        const int ntile = 2 * qb + 2;
        load_tile(0, 0); CP_COMMIT();

        for (int jb = 0; jb < ntile; ++jb) {
            const int buf = jb & 1;
            CP_WAIT0();
            __syncthreads();
            if (jb + 1 < ntile) { load_tile(buf ^ 1, jb + 1); CP_COMMIT(); }

            if (jb * 64 <= qrow0 + 15) {
                const uint32_t uK = uK0 + buf * FTILE_BYTES;
                const uint32_t uV = uV0 + buf * FTILE_BYTES;

                // S = Q K^T
                float s[8][4];
#pragma unroll
                for (int ni = 0; ni < 8; ++ni)
                    s[ni][0] = s[ni][1] = s[ni][2] = s[ni][3] = 0.f;

#pragma unroll
                for (int kk = 0; kk < 4; ++kk)
#pragma unroll
                    for (int p = 0; p < 4; ++p) {
                        const uint32_t rb = (uint32_t)(p * 16 * FSTR) * 2 + kk * 32;
                        uint32_t k4[4];
                        ldsm4(k4, uK + rb + boff);
                        mma16816(s[2*p],   qf[kk], k4 + 0);
                        mma16816(s[2*p+1], qf[kk], k4 + 2);
                    }

                // causal mask (diagonal tiles only)
                if (jb * 64 + 63 > qrow0) {
                    const int cb = jb * 64 + tg * 2;
                    const int r0 = qrow0 + g, r1 = r0 + 8;
#pragma unroll
                    for (int ni = 0; ni < 8; ++ni) {
                        int c0 = cb + ni * 8, c1 = c0 + 1;
                        if (c0 > r0) s[ni][0] = -1e30f;
                        if (c1 > r0) s[ni][1] = -1e30f;
                        if (c0 > r1) s[ni][2] = -1e30f;
                        if (c1 > r1) s[ni][3] = -1e30f;
                    }
                }

                // online softmax: max in fp32, exp via ex2.approx.f16x2
                float mt0 = -1e30f, mt1 = -1e30f;
#pragma unroll
                for (int ni = 0; ni < 8; ++ni) {
                    mt0 = fmaxf(mt0, fmaxf(s[ni][0], s[ni][1]));
                    mt1 = fmaxf(mt1, fmaxf(s[ni][2], s[ni][3]));
                }
                mt0 = fmaxf(mt0, __shfl_xor_sync(0xffffffffu, mt0, 1));
                mt0 = fmaxf(mt0, __shfl_xor_sync(0xffffffffu, mt0, 2));
                mt1 = fmaxf(mt1, __shfl_xor_sync(0xffffffffu, mt1, 1));
                mt1 = fmaxf(mt1, __shfl_xor_sync(0xffffffffu, mt1, 2));
                float mn0 = fmaxf(m0, mt0), mn1 = fmaxf(m1, mt1);
                float a0 = __expf(m0 - mn0), a1 = __expf(m1 - mn1);
                m0 = mn0; m1 = mn1;
                const float b0 = mn0 * L2E, b1 = mn1 * L2E;

                uint32_t pe0[8], pe1[8];
                float rs0 = 0.f, rs1 = 0.f;
#pragma unroll
                for (int ni = 0; ni < 8; ++ni) {
                    __half2 e01 = h2exp2(__floats2half2_rn(
                        fmaf(s[ni][0], L2E, -b0), fmaf(s[ni][1], L2E, -b0)));
                    __half2 e23 = h2exp2(__floats2half2_rn(
                        fmaf(s[ni][2], L2E, -b1), fmaf(s[ni][3], L2E, -b1)));
                    pe0[ni] = *(uint32_t*)&e01;
                    pe1[ni] = *(uint32_t*)&e23;
                    float2 f01 = __half22float2(e01);
                    float2 f23 = __half22float2(e23);
                    rs0 += f01.x + f01.y;
                    rs1 += f23.x + f23.y;
                }
                l0 = l0 * a0 + rs0;
                l1 = l1 * a1 + rs1;
#pragma unroll
                for (int ni = 0; ni < 8; ++ni) {
                    o[ni][0] *= a0; o[ni][1] *= a0;
                    o[ni][2] *= a1; o[ni][3] *= a1;
                }

                // O += P V (fp32 accum)
#pragma unroll
                for (int kk = 0; kk < 4; ++kk) {
                    uint32_t ph[4];
                    ph[0] = pe0[2*kk];     ph[1] = pe1[2*kk];
                    ph[2] = pe0[2*kk + 1]; ph[3] = pe1[2*kk + 1];
#pragma unroll
                    for (int p = 0; p < 4; ++p) {
                        const uint32_t rb = (uint32_t)(p * 16 * FSTR) * 2 + kk * 32;
                        uint32_t v4[4];
                        ldsm4(v4, uV + rb + boff);
                        mma16816(o[2*p],   ph, v4 + 0);
                        mma16816(o[2*p+1], ph, v4 + 2);
                    }
                }
            }
        }

        // finalize this pass
        l0 += __shfl_xor_sync(0xffffffffu, l0, 1);
        l0 += __shfl_xor_sync(0xffffffffu, l0, 2);
        l1 += __shfl_xor_sync(0xffffffffu, l1, 1);
        l1 += __shfl_xor_sync(0xffffffffu, l1, 2);
        const float inv0 = 1.f / l0, inv1 = 1.f / l1;

        const int r0 = qrow0 + g, r1 = r0 + 8;
#pragma unroll
        for (int ni = 0; ni < 8; ++ni) {
            const int col = h * HD + ni * 8 + tg * 2;
            *(__half2*)&g_ao[(size_t)(b * SEQ + r0) * DIM + col] =
                __floats2half2_rn(o[ni][0] * inv0, o[ni][1] * inv0);
            *(__half2*)&g_ao[(size_t)(b * SEQ + r1) * DIM + col] =
                __floats2half2_rn(o[ni][2] * inv1, o[ni][3] * inv1);
        }
        __syncthreads();   // pass state / smem reuse boundary
    }
}

// ---------------- launcher ---------------------------------------------------
extern "C" void kernel_launch(void* const* d_in, const int* in_sizes, int n_in,
                              void* d_out, int out_size)
{
    const float* x     = (const float*)d_in[0];   // [2,2048,2048]
    const float* fc    = (const float*)d_in[1];   // [2048,32,2]
    // d_in[2] = mask (causal, hardcoded)
    const float* wqkv  = (const float*)d_in[3];   // [3072,2048]
    const float* wo    = (const float*)d_in[4];   // [2048,2048]
    float* out = (float*)d_out;                   // [2,2048,2048]

    void *p_x, *p_wq, *p_ao, *p_wo;
    cudaGetSymbolAddress(&p_x,  g_x);
    cudaGetSymbolAddress(&p_wq, g_wq);
    cudaGetSymbolAddress(&p_ao, g_ao);
    cudaGetSymbolAddress(&p_wo, g_wo);

    cudaFuncSetAttribute(gemm_qkv_kernel,
                         cudaFuncAttributeMaxDynamicSharedMemorySize, GT_SMEM_BYTES);
    cudaFuncSetAttribute(gemm_hmma_kernel,
                         cudaFuncAttributeMaxDynamicSharedMemorySize, GT_SMEM_BYTES);

    const int M = BSZ * SEQ;                      // 4096

    // 0) x + wqkv fp32->fp16 (wo conversion fused into flash prologue)
    conv_xw_kernel<<<(CN1 + CN2) / 256, 256>>>(x, wqkv);

    // 1) QKV projection with fused RoPE + scatter -> g_q / g_k / g_v
    gemm_qkv_kernel<<<dim3(QKV_N / 128, M / 128), 256, GT_SMEM_BYTES>>>(
        (const __half*)p_x, (const __half*)p_wq, fc, DIM);

    // 2) causal flash attention (paired Q-tiles) + fused wo conversion
    flash_hmma_kernel<<<dim3(SEQ / 256, NH, BSZ), 256>>>(wo);

    // 3) output projection -> fp32
    gemm_hmma_kernel<<<dim3(DIM / 128, M / 128), 256, GT_SMEM_BYTES>>>(
        (const __half*)p_ao, (const __half*)p_wo,
        out, M, DIM, DIM);
}